// round 1
// baseline (speedup 1.0000x reference)
#include <cuda_runtime.h>

// LSTM: B=2048, T=512, F=64, H=128. Gate order i,f,g,o. out[b][t][h] fp32.
// Each block owns MB batch rows for the entire time loop (rows are independent).

#define T_DIM 512
#define F_DIM 64
#define H_DIM 128
#define G_DIM 512              // 4*H
#define MB    8                // batch rows per block
#define NTH   512              // threads per block, thread j -> gate column j
#define KREG  96               // unified-k rows held in registers (Wx 0..63 + Wh 0..31)
#define KSMEM 96               // Wh rows 32..127 held in smem
#define KTOT  (F_DIM + H_DIM)  // 192
#define PAD   12               // activation row pad (floats): 48B, 16B-aligned

__device__ __forceinline__ float sigmoidf_(float v) {
    return 1.0f / (1.0f + __expf(-v));
}

__global__ __launch_bounds__(NTH, 1)
void lstm_fused(const float* __restrict__ x,
                const float* __restrict__ Wx,
                const float* __restrict__ Wh,
                const float* __restrict__ bias,
                float* __restrict__ out)
{
    extern __shared__ float sm[];
    float* sW = sm;                          // [KSMEM][G_DIM]   192 KB
    float* sZ = sW + KSMEM * G_DIM;          // [MB][G_DIM]       16 KB
    float* sC = sZ + MB * G_DIM;             // [MB][H_DIM]        4 KB
    float* sA = sC + MB * H_DIM;             // [KTOT][PAD]        9 KB (transposed acts)

    const int tid = threadIdx.x;
    const int j = tid;                       // gate column 0..511
    const long b0 = (long)blockIdx.x * MB;

    // ---- load weights ----
    float WR[KREG];
    #pragma unroll
    for (int q = 0; q < F_DIM; q++) WR[q] = Wx[q * G_DIM + j];
    #pragma unroll
    for (int q = 0; q < KREG - F_DIM; q++) WR[F_DIM + q] = Wh[q * G_DIM + j];
    for (int kk = 0; kk < KSMEM; kk++)
        sW[kk * G_DIM + j] = Wh[(KREG - F_DIM + kk) * G_DIM + j];
    const float bj = bias[j];

    // ---- zero state ----
    for (int i = tid; i < MB * H_DIM; i += NTH) sC[i] = 0.0f;
    for (int i = tid; i < KTOT * PAD; i += NTH) sA[i] = 0.0f;

    // x loader mapping: thread -> (row, feature), one element per step
    const int xr = tid >> 6;                 // 0..7
    const int xk = tid & 63;                 // 0..63
    const float* xptr = x + (b0 + xr) * (long)(T_DIM * F_DIM) + xk;
    float xreg = xptr[0];

    __syncthreads();

    for (int t = 0; t < T_DIM; t++) {
        // stage x_t into transposed activation buffer (k rows 0..63)
        sA[xk * PAD + xr] = xreg;
        __syncthreads();                     // [A] x + h(prev gate) visible
        if (t + 1 < T_DIM) xreg = xptr[(t + 1) * F_DIM];  // prefetch under FMA loop

        float acc[MB];
        #pragma unroll
        for (int r = 0; r < MB; r++) acc[r] = bj;

        // register-weight region: k = 0..95 (Wx all rows, Wh rows 0..31)
        #pragma unroll
        for (int k = 0; k < KREG; k++) {
            float4 a0 = *(const float4*)(sA + k * PAD);
            float4 a1 = *(const float4*)(sA + k * PAD + 4);
            float w = WR[k];
            acc[0] = fmaf(w, a0.x, acc[0]);
            acc[1] = fmaf(w, a0.y, acc[1]);
            acc[2] = fmaf(w, a0.z, acc[2]);
            acc[3] = fmaf(w, a0.w, acc[3]);
            acc[4] = fmaf(w, a1.x, acc[4]);
            acc[5] = fmaf(w, a1.y, acc[5]);
            acc[6] = fmaf(w, a1.z, acc[6]);
            acc[7] = fmaf(w, a1.w, acc[7]);
        }
        // smem-weight region: k = 96..191 (Wh rows 32..127), coalesced weight loads
        #pragma unroll 8
        for (int k = KREG; k < KTOT; k++) {
            float4 a0 = *(const float4*)(sA + k * PAD);
            float4 a1 = *(const float4*)(sA + k * PAD + 4);
            float w = sW[(k - KREG) * G_DIM + j];
            acc[0] = fmaf(w, a0.x, acc[0]);
            acc[1] = fmaf(w, a0.y, acc[1]);
            acc[2] = fmaf(w, a0.z, acc[2]);
            acc[3] = fmaf(w, a0.w, acc[3]);
            acc[4] = fmaf(w, a1.x, acc[4]);
            acc[5] = fmaf(w, a1.y, acc[5]);
            acc[6] = fmaf(w, a1.z, acc[6]);
            acc[7] = fmaf(w, a1.w, acc[7]);
        }

        #pragma unroll
        for (int r = 0; r < MB; r++) sZ[r * G_DIM + j] = acc[r];
        __syncthreads();                     // [B] z visible

        // gate combine: MB*H = 1024 items, 2 per thread
        #pragma unroll
        for (int it = 0; it < (MB * H_DIM) / NTH; it++) {
            int idx = tid + it * NTH;
            int r  = idx >> 7;
            int jh = idx & (H_DIM - 1);
            const float* zr = sZ + r * G_DIM;
            float ig = sigmoidf_(zr[jh]);
            float fg = sigmoidf_(zr[jh + H_DIM]);
            float gg = tanhf(zr[jh + 2 * H_DIM]);
            float og = sigmoidf_(zr[jh + 3 * H_DIM]);
            float c = fmaf(fg, sC[r * H_DIM + jh], ig * gg);
            sC[r * H_DIM + jh] = c;
            float h = og * tanhf(c);
            sA[(F_DIM + jh) * PAD + r] = h;  // k rows 64..191
            out[(b0 + r) * (long)(T_DIM * H_DIM) + (long)t * H_DIM + jh] = h;
        }
        // no barrier here: next iter's x-write targets k rows 0..63 (disjoint from
        // gate writes), and barrier [A] orders gate's h writes before the FMA reads.
    }
}

extern "C" void kernel_launch(void* const* d_in, const int* in_sizes, int n_in,
                              void* d_out, int out_size) {
    const float* x  = (const float*)d_in[0];   // [B,T,F]
    const float* Wx = (const float*)d_in[1];   // [F,4H]
    const float* Wh = (const float*)d_in[2];   // [H,4H]
    const float* b  = (const float*)d_in[3];   // [4H]
    float* out = (float*)d_out;                // [B,T,H]

    const int Bdim = in_sizes[0] / (T_DIM * F_DIM);   // 2048
    const size_t smem = (size_t)(KSMEM * G_DIM + MB * G_DIM + MB * H_DIM + KTOT * PAD)
                        * sizeof(float);              // 226,304 B

    cudaFuncSetAttribute(lstm_fused, cudaFuncAttributeMaxDynamicSharedMemorySize,
                         (int)smem);

    dim3 grid(Bdim / MB);   // 256 blocks
    dim3 block(NTH);
    lstm_fused<<<grid, block, smem>>>(x, Wx, Wh, b, out);
}

// round 3
// speedup vs baseline: 1.0022x; 1.0022x over previous
#include <cuda_runtime.h>

// LSTM: B=2048, T=512, F=64, H=128. Gate order i,f,g,o. out[b][t][h] fp32.
// Each block owns MB batch rows for the entire time loop (rows are independent).

#define T_DIM 512
#define F_DIM 64
#define H_DIM 128
#define G_DIM 512              // 4*H
#define MB    8                // batch rows per block
#define NTH   512              // threads per block, thread j -> gate column j
#define KREG  96               // unified-k rows held in registers (Wx 0..63 + Wh 0..31)
#define KSMEM 96               // Wh rows 32..127 held in smem
#define KTOT  (F_DIM + H_DIM)  // 192
#define PAD   12               // activation row pad (floats): 48B, 16B-aligned

__device__ __forceinline__ float sigmoidf_(float v) {
    return 1.0f / (1.0f + __expf(-v));
}

__global__ __launch_bounds__(NTH, 1)
void lstm_fused(const float* __restrict__ x,
                const float* __restrict__ Wx,
                const float* __restrict__ Wh,
                const float* __restrict__ bias,
                float* __restrict__ out)
{
    extern __shared__ float sm[];
    float* sW = sm;                          // [KSMEM][G_DIM]   192 KB
    float* sZ = sW + KSMEM * G_DIM;          // [MB][G_DIM]       16 KB
    float* sC = sZ + MB * G_DIM;             // [MB][H_DIM]        4 KB
    float* sA = sC + MB * H_DIM;             // [KTOT][PAD]        9 KB (transposed acts)

    const int tid = threadIdx.x;
    const int j = tid;                       // gate column 0..511
    const long b0 = (long)blockIdx.x * MB;

    // ---- load weights ----
    float WR[KREG];
    #pragma unroll
    for (int q = 0; q < F_DIM; q++) WR[q] = Wx[q * G_DIM + j];
    #pragma unroll
    for (int q = 0; q < KREG - F_DIM; q++) WR[F_DIM + q] = Wh[q * G_DIM + j];
    for (int kk = 0; kk < KSMEM; kk++)
        sW[kk * G_DIM + j] = Wh[(KREG - F_DIM + kk) * G_DIM + j];
    const float bj = bias[j];

    // ---- zero state ----
    for (int i = tid; i < MB * H_DIM; i += NTH) sC[i] = 0.0f;
    for (int i = tid; i < KTOT * PAD; i += NTH) sA[i] = 0.0f;

    // x loader mapping: thread -> (row, feature), one element per step
    const int xr = tid >> 6;                 // 0..7
    const int xk = tid & 63;                 // 0..63
    const float* xptr = x + (b0 + xr) * (long)(T_DIM * F_DIM) + xk;
    float xreg = xptr[0];

    __syncthreads();

    for (int t = 0; t < T_DIM; t++) {
        // stage x_t into transposed activation buffer (k rows 0..63)
        sA[xk * PAD + xr] = xreg;
        __syncthreads();                     // [A] x + h(prev gate) visible
        if (t + 1 < T_DIM) xreg = xptr[(t + 1) * F_DIM];  // prefetch under FMA loop

        float acc[MB];
        #pragma unroll
        for (int r = 0; r < MB; r++) acc[r] = bj;

        // register-weight region: k = 0..95 (Wx all rows, Wh rows 0..31)
        #pragma unroll
        for (int k = 0; k < KREG; k++) {
            float4 a0 = *(const float4*)(sA + k * PAD);
            float4 a1 = *(const float4*)(sA + k * PAD + 4);
            float w = WR[k];
            acc[0] = fmaf(w, a0.x, acc[0]);
            acc[1] = fmaf(w, a0.y, acc[1]);
            acc[2] = fmaf(w, a0.z, acc[2]);
            acc[3] = fmaf(w, a0.w, acc[3]);
            acc[4] = fmaf(w, a1.x, acc[4]);
            acc[5] = fmaf(w, a1.y, acc[5]);
            acc[6] = fmaf(w, a1.z, acc[6]);
            acc[7] = fmaf(w, a1.w, acc[7]);
        }
        // smem-weight region: k = 96..191 (Wh rows 32..127), coalesced weight loads
        #pragma unroll 8
        for (int k = KREG; k < KTOT; k++) {
            float4 a0 = *(const float4*)(sA + k * PAD);
            float4 a1 = *(const float4*)(sA + k * PAD + 4);
            float w = sW[(k - KREG) * G_DIM + j];
            acc[0] = fmaf(w, a0.x, acc[0]);
            acc[1] = fmaf(w, a0.y, acc[1]);
            acc[2] = fmaf(w, a0.z, acc[2]);
            acc[3] = fmaf(w, a0.w, acc[3]);
            acc[4] = fmaf(w, a1.x, acc[4]);
            acc[5] = fmaf(w, a1.y, acc[5]);
            acc[6] = fmaf(w, a1.z, acc[6]);
            acc[7] = fmaf(w, a1.w, acc[7]);
        }

        #pragma unroll
        for (int r = 0; r < MB; r++) sZ[r * G_DIM + j] = acc[r];
        __syncthreads();                     // [B] z visible

        // gate combine: MB*H = 1024 items, 2 per thread
        #pragma unroll
        for (int it = 0; it < (MB * H_DIM) / NTH; it++) {
            int idx = tid + it * NTH;
            int r  = idx >> 7;
            int jh = idx & (H_DIM - 1);
            const float* zr = sZ + r * G_DIM;
            float ig = sigmoidf_(zr[jh]);
            float fg = sigmoidf_(zr[jh + H_DIM]);
            float gg = tanhf(zr[jh + 2 * H_DIM]);
            float og = sigmoidf_(zr[jh + 3 * H_DIM]);
            float c = fmaf(fg, sC[r * H_DIM + jh], ig * gg);
            sC[r * H_DIM + jh] = c;
            float h = og * tanhf(c);
            sA[(F_DIM + jh) * PAD + r] = h;  // k rows 64..191
            out[(b0 + r) * (long)(T_DIM * H_DIM) + (long)t * H_DIM + jh] = h;
        }
        // no barrier here: next iter's x-write targets k rows 0..63 (disjoint from
        // gate writes), and barrier [A] orders gate's h writes before the FMA reads.
    }
}

extern "C" void kernel_launch(void* const* d_in, const int* in_sizes, int n_in,
                              void* d_out, int out_size) {
    const float* x  = (const float*)d_in[0];   // [B,T,F]
    const float* Wx = (const float*)d_in[1];   // [F,4H]
    const float* Wh = (const float*)d_in[2];   // [H,4H]
    const float* b  = (const float*)d_in[3];   // [4H]
    float* out = (float*)d_out;                // [B,T,H]

    const int Bdim = in_sizes[0] / (T_DIM * F_DIM);   // 2048
    const size_t smem = (size_t)(KSMEM * G_DIM + MB * G_DIM + MB * H_DIM + KTOT * PAD)
                        * sizeof(float);              // 226,304 B

    cudaFuncSetAttribute(lstm_fused, cudaFuncAttributeMaxDynamicSharedMemorySize,
                         (int)smem);

    dim3 grid(Bdim / MB);   // 256 blocks
    dim3 block(NTH);
    lstm_fused<<<grid, block, smem>>>(x, Wx, Wh, b, out);
}